// round 1
// baseline (speedup 1.0000x reference)
#include <cuda_runtime.h>

// SpatialTransformer: affine grid + bilinear sampling.
// image: [B=16, H=256, W=256, C=64] fp32 (channels-last, contiguous)
// theta: [B=16, 6] fp32
// out:   [B=16, OH=256, OW=256, C=64] fp32

constexpr int B_  = 16;
constexpr int H_  = 256;
constexpr int W_  = 256;
constexpr int C_  = 64;
constexpr int OH_ = 256;
constexpr int OW_ = 256;

// 16 threads per output pixel, each handles one float4 (4 channels).
// C = 64 floats = 16 float4 chunks.
__global__ __launch_bounds__(256) void stn_kernel(
    const float* __restrict__ img,
    const float* __restrict__ theta,
    float* __restrict__ out)
{
    const int gid = blockIdx.x * blockDim.x + threadIdx.x;
    const int c4  = gid & 15;       // float4 chunk within channel dim
    const int pix = gid >> 4;       // global output pixel index

    // total pixels = 16*256*256 = 1048576; grid sized exactly, no bounds check needed
    const int ox   = pix & (OW_ - 1);
    const int rest = pix >> 8;          // pix / OW_
    const int oy   = rest & (OH_ - 1);
    const int b    = rest >> 8;         // rest / OH_

    // theta row for this batch (broadcast via L1/L2 const path)
    const float t0 = __ldg(theta + b * 6 + 0);
    const float t1 = __ldg(theta + b * 6 + 1);
    const float t2 = __ldg(theta + b * 6 + 2);
    const float t3 = __ldg(theta + b * 6 + 3);
    const float t4 = __ldg(theta + b * 6 + 4);
    const float t5 = __ldg(theta + b * 6 + 5);

    // normalized grid coords, linspace(-1, 1, N): step = 2/(N-1)
    const float xs = fmaf((float)ox, 2.0f / (OW_ - 1), -1.0f);
    const float ys = fmaf((float)oy, 2.0f / (OH_ - 1), -1.0f);

    const float xt = fmaf(t0, xs, fmaf(t1, ys, t2));
    const float yt = fmaf(t3, xs, fmaf(t4, ys, t5));

    const float x = 0.5f * (xt + 1.0f) * (float)W_;
    const float y = 0.5f * (yt + 1.0f) * (float)H_;

    const float xf = floorf(x);
    const float yf = floorf(y);

    int ix0 = min(max((int)xf,     0), W_ - 1);
    int ix1 = min(max((int)xf + 1, 0), W_ - 1);
    int iy0 = min(max((int)yf,     0), H_ - 1);
    int iy1 = min(max((int)yf + 1, 0), H_ - 1);

    // weights use CLIPPED corner coords cast back to float (matches reference)
    const float x0f = (float)ix0, x1f = (float)ix1;
    const float y0f = (float)iy0, y1f = (float)iy1;
    const float wa = (x1f - x) * (y1f - y);
    const float wb = (x1f - x) * (y - y0f);
    const float wc = (x - x0f) * (y1f - y);
    const float wd = (x - x0f) * (y - y0f);

    // float4-granular indexing: ((b*H + y)*W + x) * 16 + c4   (max ~16.7M, fits int)
    const int rowb = b * H_;
    const float4* __restrict__ img4 = (const float4*)img;
    const float4 Ia = __ldg(img4 + ((rowb + iy0) * W_ + ix0) * (C_ / 4) + c4);
    const float4 Ib = __ldg(img4 + ((rowb + iy1) * W_ + ix0) * (C_ / 4) + c4);
    const float4 Ic = __ldg(img4 + ((rowb + iy0) * W_ + ix1) * (C_ / 4) + c4);
    const float4 Id = __ldg(img4 + ((rowb + iy1) * W_ + ix1) * (C_ / 4) + c4);

    float4 o;
    o.x = fmaf(wa, Ia.x, fmaf(wb, Ib.x, fmaf(wc, Ic.x, wd * Id.x)));
    o.y = fmaf(wa, Ia.y, fmaf(wb, Ib.y, fmaf(wc, Ic.y, wd * Id.y)));
    o.z = fmaf(wa, Ia.z, fmaf(wb, Ib.z, fmaf(wc, Ic.z, wd * Id.z)));
    o.w = fmaf(wa, Ia.w, fmaf(wb, Ib.w, fmaf(wc, Ic.w, wd * Id.w)));

    ((float4*)out)[pix * (C_ / 4) + c4] = o;
}

extern "C" void kernel_launch(void* const* d_in, const int* in_sizes, int n_in,
                              void* d_out, int out_size)
{
    const float* img   = (const float*)d_in[0];
    const float* theta = (const float*)d_in[1];
    float* out = (float*)d_out;

    // total threads = B*OH*OW * 16 = 16,777,216 -> 65536 blocks of 256
    const int total_pix = B_ * OH_ * OW_;
    const int threads   = 256;
    const int blocks    = (total_pix * 16) / threads;

    stn_kernel<<<blocks, threads>>>(img, theta, out);
}

// round 4
// speedup vs baseline: 1.2338x; 1.2338x over previous
#include <cuda_runtime.h>

// SpatialTransformer: affine grid + bilinear sampling, with corner-register
// reuse along the oy walk (corners shift by ~1 input row per output row).
// image: [B=16, H=256, W=256, C=64] fp32, theta: [B=16, 6], out same as image.

constexpr int B_  = 16;
constexpr int H_  = 256;
constexpr int W_  = 256;
constexpr int C_  = 64;
constexpr int OH_ = 256;
constexpr int OW_ = 256;
constexpr int K_  = 8;   // oy pixels per thread

__global__ __launch_bounds__(256) void stn_kernel(
    const float* __restrict__ img,
    const float* __restrict__ theta,
    float* __restrict__ out)
{
    const int gid = blockIdx.x * blockDim.x + threadIdx.x;
    const int c4  = gid & 15;          // float4 chunk (4 channels)
    const int t   = gid >> 4;          // pixel-column index
    const int ox  = t & (OW_ - 1);
    const int t2  = t >> 8;
    const int oyb = (t2 & (OH_ / K_ - 1)) * K_;
    const int b   = t2 >> 5;           // OH_/K_ = 32 -> shift 5

    const float th0 = __ldg(theta + b * 6 + 0);
    const float th1 = __ldg(theta + b * 6 + 1);
    const float th2 = __ldg(theta + b * 6 + 2);
    const float th3 = __ldg(theta + b * 6 + 3);
    const float th4 = __ldg(theta + b * 6 + 4);
    const float th5 = __ldg(theta + b * 6 + 5);

    // xs fixed for this thread; fold theta into per-column constants:
    //   xt = th1*ys + (th0*xs + th2),  yt = th4*ys + (th3*xs + th5)
    const float xs = fmaf((float)ox, 2.0f / (OW_ - 1), -1.0f);
    const float xc = fmaf(th0, xs, th2);
    const float yc = fmaf(th3, xs, th5);

    const float4* __restrict__ img4 = (const float4*)img + c4;
    float4* __restrict__ out4 =
        (float4*)out + (((b * OH_ + oyb) * OW_ + ox) * (C_ / 4) + c4);

    const int rowb = b * H_;

    int px0 = -0x40000000, px1 = -0x40000000, py0 = -0x40000000, py1 = -0x40000000;
    float4 Ia, Ib, Ic, Id;
    Ia = Ib = Ic = Id = make_float4(0.f, 0.f, 0.f, 0.f);

#pragma unroll
    for (int k = 0; k < K_; k++) {
        const float ys = fmaf((float)(oyb + k), 2.0f / (OH_ - 1), -1.0f);
        const float x  = (fmaf(th1, ys, xc) + 1.0f) * (0.5f * (float)W_);
        const float y  = (fmaf(th4, ys, yc) + 1.0f) * (0.5f * (float)H_);

        const float xf = floorf(x);
        const float yf = floorf(y);
        const int ix0 = min(max((int)xf,     0), W_ - 1);
        const int ix1 = min(max((int)xf + 1, 0), W_ - 1);
        const int iy0 = min(max((int)yf,     0), H_ - 1);
        const int iy1 = min(max((int)yf + 1, 0), H_ - 1);

        const bool samex = (ix0 == px0) && (ix1 == px1);
        if (samex && iy0 == py0 && iy1 == py1) {
            // identical corners -> full register reuse, zero loads
        } else if (samex && iy0 == py1) {
            // shifted one input row down: top corners = previous bottom corners
            Ia = Ib;
            Ic = Id;
            Ib = __ldg(img4 + ((rowb + iy1) * W_ + ix0) * (C_ / 4));
            Id = __ldg(img4 + ((rowb + iy1) * W_ + ix1) * (C_ / 4));
        } else {
            Ia = __ldg(img4 + ((rowb + iy0) * W_ + ix0) * (C_ / 4));
            Ib = __ldg(img4 + ((rowb + iy1) * W_ + ix0) * (C_ / 4));
            Ic = __ldg(img4 + ((rowb + iy0) * W_ + ix1) * (C_ / 4));
            Id = __ldg(img4 + ((rowb + iy1) * W_ + ix1) * (C_ / 4));
        }
        px0 = ix0; px1 = ix1; py0 = iy0; py1 = iy1;

        // weights from CLIPPED corners cast back to float (matches reference)
        const float x0f = (float)ix0, x1f = (float)ix1;
        const float y0f = (float)iy0, y1f = (float)iy1;
        const float wa = (x1f - x) * (y1f - y);
        const float wb = (x1f - x) * (y - y0f);
        const float wc = (x - x0f) * (y1f - y);
        const float wd = (x - x0f) * (y - y0f);

        float4 o;
        o.x = fmaf(wa, Ia.x, fmaf(wb, Ib.x, fmaf(wc, Ic.x, wd * Id.x)));
        o.y = fmaf(wa, Ia.y, fmaf(wb, Ib.y, fmaf(wc, Ic.y, wd * Id.y)));
        o.z = fmaf(wa, Ia.z, fmaf(wb, Ib.z, fmaf(wc, Ic.z, wd * Id.z)));
        o.w = fmaf(wa, Ia.w, fmaf(wb, Ib.w, fmaf(wc, Ic.w, wd * Id.w)));

        *out4 = o;
        out4 += OW_ * (C_ / 4);
    }
}

extern "C" void kernel_launch(void* const* d_in, const int* in_sizes, int n_in,
                              void* d_out, int out_size)
{
    const float* img   = (const float*)d_in[0];
    const float* theta = (const float*)d_in[1];
    float* out = (float*)d_out;

    // threads = B*OW*(OH/K)*16 = 16*256*32*16 = 2,097,152 -> 8192 blocks
    const int threads = 256;
    const int blocks  = (B_ * OW_ * (OH_ / K_) * 16) / threads;

    stn_kernel<<<blocks, threads>>>(img, theta, out);
}